// round 6
// baseline (speedup 1.0000x reference)
#include <cuda_runtime.h>
#include <cstdint>

// out[t, v] = bias[v] + sum_{q=0..3} W[v][q] * cos(x[t])^(q+1)
// (closed form of the CNOT-permuted Ry product state; phase cancels in |psi|^2)
//
// Persistent single-wave streaming kernel: 168MB stores, 4MB loads.
// grid = 148 SMs x 12 CTAs (NT=160, 5 warps, regs~40 -> 60 warps/SM resident
// for the whole run; no wave transitions / ramp troughs). Each CTA grid-strides
// over CHUNK-sized output tiles. Thread owns fixed v-group vv=tid%10, coeffs
// packed in regs as f32x2; per tile: 8 front-batched LDG.32 (MLP=8), then 8
// independent [5-FMA cos poly -> 8 fma.f32x2 Horner -> STG.128] chains.
// Warp stores 512 contiguous bytes.

#define NT    160
#define ITERS 8
#define CHUNK (NT * ITERS)      // 1280 float4 per tile; %10==0 -> vv loop-invariant
#define SMS   148
#define CTAS_PER_SM 12

#define PACK2(o, lo, hi) \
    asm("mov.b64 %0, {%1, %2};" : "=l"(o) : "f"(lo), "f"(hi))
#define FMA2(d, a, b, c) \
    asm("fma.rn.f32x2 %0, %1, %2, %3;" : "=l"(d) : "l"(a), "l"(b), "l"(c))

__device__ __forceinline__ void eval_store(
    float xv,
    unsigned long long c0a, unsigned long long c0b,
    unsigned long long c1a, unsigned long long c1b,
    unsigned long long c2a, unsigned long long c2b,
    unsigned long long c3a, unsigned long long c3b,
    unsigned long long c4a, unsigned long long c4b,
    float4* __restrict__ dst)
{
    // cos(xv) for xv in [0,1): even Taylor, rel err < 3e-9
    const float y = xv * xv;
    float u = fmaf(y, -2.7557319e-07f,  2.4801587e-05f);
    u = fmaf(y, u, -1.3888889e-03f);
    u = fmaf(y, u,  4.1666667e-02f);
    u = fmaf(y, u, -5.0000000e-01f);
    u = fmaf(y, u,  1.0000000e+00f);

    unsigned long long pu;
    PACK2(pu, u, u);

    // Horner: r = c0 + u*(c1 + u*(c2 + u*(c3 + u*c4))), two packed halves
    unsigned long long r01, r23;
    FMA2(r01, c4a, pu, c3a);
    FMA2(r23, c4b, pu, c3b);
    FMA2(r01, r01, pu, c2a);
    FMA2(r23, r23, pu, c2b);
    FMA2(r01, r01, pu, c1a);
    FMA2(r23, r23, pu, c1b);
    FMA2(r01, r01, pu, c0a);
    FMA2(r23, r23, pu, c0b);

    float2 lo = *(float2*)&r01;
    float2 hi = *(float2*)&r23;
    *dst = make_float4(lo.x, lo.y, hi.x, hi.y);
}

__global__ void __launch_bounds__(NT)
qmodel_kernel(const float* __restrict__ x,
              const float* __restrict__ W,     // (40,4) row-major
              const float* __restrict__ bias,  // (40,)
              float4* __restrict__ out4,       // (SEQ*10,) float4
              int total4,                      // SEQ*10
              int nchunks)
{
    const int tid = threadIdx.x;
    const int vv  = tid % 10;
    const int lt  = tid / 10;                  // 0..15

    // ---- packed coefficients for outputs v0..v0+3 (kernel-invariant) ----
    const int v0 = vv * 4;
    const float4 w0 = ((const float4*)W)[v0 + 0];
    const float4 w1 = ((const float4*)W)[v0 + 1];
    const float4 w2 = ((const float4*)W)[v0 + 2];
    const float4 w3 = ((const float4*)W)[v0 + 3];
    const float4 bb = *(const float4*)(bias + v0);

    unsigned long long c0a, c0b, c1a, c1b, c2a, c2b, c3a, c3b, c4a, c4b;
    PACK2(c0a, bb.x, bb.y);  PACK2(c0b, bb.z, bb.w);
    PACK2(c1a, w0.x, w1.x);  PACK2(c1b, w2.x, w3.x);
    PACK2(c2a, w0.y, w1.y);  PACK2(c2b, w2.y, w3.y);
    PACK2(c3a, w0.z, w1.z);  PACK2(c3b, w2.z, w3.z);
    PACK2(c4a, w0.w, w1.w);  PACK2(c4b, w2.w, w3.w);

    for (int c = blockIdx.x; c < nchunks; c += gridDim.x) {
        const int base = c * CHUNK;            // float4 index, % 10 == 0
        const int t0   = base / 10 + lt;

        if (base + CHUNK <= total4) {
            // hot path: front-batch all loads (MLP = ITERS), then indep chains
            float xv[ITERS];
            #pragma unroll
            for (int i = 0; i < ITERS; ++i)
                xv[i] = x[t0 + (NT / 10) * i];

            #pragma unroll
            for (int i = 0; i < ITERS; ++i)
                eval_store(xv[i], c0a,c0b,c1a,c1b,c2a,c2b,c3a,c3b,c4a,c4b,
                           out4 + base + i * NT + tid);
        } else {
            #pragma unroll
            for (int i = 0; i < ITERS; ++i) {
                const int g = base + i * NT + tid;
                if (g < total4)
                    eval_store(x[t0 + (NT / 10) * i],
                               c0a,c0b,c1a,c1b,c2a,c2b,c3a,c3b,c4a,c4b,
                               out4 + g);
            }
        }
    }
}

extern "C" void kernel_launch(void* const* d_in, const int* in_sizes, int n_in,
                              void* d_out, int out_size)
{
    const float* x    = (const float*)d_in[0];
    // d_in[1] = q_weights: unused (global phase cancels in |psi|^2)
    const float* W    = (const float*)d_in[2];
    const float* bias = (const float*)d_in[3];
    float4* out4      = (float4*)d_out;

    const int seq     = in_sizes[0];
    const int total4  = seq * 10;
    const int nchunks = (total4 + CHUNK - 1) / CHUNK;       // 8192 for SEQ=2^20
    int grid = SMS * CTAS_PER_SM;                            // 1776: one full wave
    if (grid > nchunks) grid = nchunks;
    qmodel_kernel<<<grid, NT>>>(x, W, bias, out4, total4, nchunks);
}

// round 7
// speedup vs baseline: 1.0615x; 1.0615x over previous
#include <cuda_runtime.h>
#include <cstdint>

// out[t, v] = bias[v] + sum_{q=0..3} W[v][q] * cos(x[t])^(q+1)
// (closed form of the CNOT-permuted Ry product state; phase cancels in |psi|^2)
//
// Steady-state DRAM-write-drain bound: 168MB out + 4MB in per launch,
// period ~= 172MB / ~5.9TB/s sustained. Kernel side: minimal issues per
// STG.128, deep load MLP, fully coalesced 512B warp stores.
//   - thread owns fixed v-group vv=tid%10, coeffs packed in regs (f32x2)
//   - 16 front-batched __ldcs loads of x (MLP=16), then 16 independent
//     [5-FMA cos poly -> 8 fma.f32x2 Horner -> STG.128] chains
//   - CTA writes 40KB contiguous; grid 4096 covers SEQ=2^20 exactly

#define NT    160
#define ITERS 16
#define CHUNK (NT * ITERS)   // 2560 float4 per block; %10==0 -> vv loop-invariant

#define PACK2(o, lo, hi) \
    asm("mov.b64 %0, {%1, %2};" : "=l"(o) : "f"(lo), "f"(hi))
#define FMA2(d, a, b, c) \
    asm("fma.rn.f32x2 %0, %1, %2, %3;" : "=l"(d) : "l"(a), "l"(b), "l"(c))

__device__ __forceinline__ void eval_store(
    float xv,
    unsigned long long c0a, unsigned long long c0b,
    unsigned long long c1a, unsigned long long c1b,
    unsigned long long c2a, unsigned long long c2b,
    unsigned long long c3a, unsigned long long c3b,
    unsigned long long c4a, unsigned long long c4b,
    float4* __restrict__ dst)
{
    // cos(xv) for xv in [0,1): even Taylor, rel err < 3e-9
    const float y = xv * xv;
    float u = fmaf(y, -2.7557319e-07f,  2.4801587e-05f);
    u = fmaf(y, u, -1.3888889e-03f);
    u = fmaf(y, u,  4.1666667e-02f);
    u = fmaf(y, u, -5.0000000e-01f);
    u = fmaf(y, u,  1.0000000e+00f);

    unsigned long long pu;
    PACK2(pu, u, u);

    // Horner: r = c0 + u*(c1 + u*(c2 + u*(c3 + u*c4))), two packed halves
    unsigned long long r01, r23;
    FMA2(r01, c4a, pu, c3a);
    FMA2(r23, c4b, pu, c3b);
    FMA2(r01, r01, pu, c2a);
    FMA2(r23, r23, pu, c2b);
    FMA2(r01, r01, pu, c1a);
    FMA2(r23, r23, pu, c1b);
    FMA2(r01, r01, pu, c0a);
    FMA2(r23, r23, pu, c0b);

    float2 lo = *(float2*)&r01;
    float2 hi = *(float2*)&r23;
    *dst = make_float4(lo.x, lo.y, hi.x, hi.y);
}

__global__ void __launch_bounds__(NT)
qmodel_kernel(const float* __restrict__ x,
              const float* __restrict__ W,     // (40,4) row-major
              const float* __restrict__ bias,  // (40,)
              float4* __restrict__ out4,       // (SEQ*10,) float4
              int total4)                      // SEQ*10
{
    const int tid  = threadIdx.x;
    const int base = blockIdx.x * CHUNK;       // float4 index, % 10 == 0
    const int vv   = tid % 10;
    const int t0   = base / 10 + tid / 10;     // first t for this thread

    // ---- packed coefficients for outputs v0..v0+3 (loop-invariant) ----
    const int v0 = vv * 4;
    const float4 w0 = ((const float4*)W)[v0 + 0];
    const float4 w1 = ((const float4*)W)[v0 + 1];
    const float4 w2 = ((const float4*)W)[v0 + 2];
    const float4 w3 = ((const float4*)W)[v0 + 3];
    const float4 bb = *(const float4*)(bias + v0);

    unsigned long long c0a, c0b, c1a, c1b, c2a, c2b, c3a, c3b, c4a, c4b;
    PACK2(c0a, bb.x, bb.y);  PACK2(c0b, bb.z, bb.w);
    PACK2(c1a, w0.x, w1.x);  PACK2(c1b, w2.x, w3.x);
    PACK2(c2a, w0.y, w1.y);  PACK2(c2b, w2.y, w3.y);
    PACK2(c3a, w0.z, w1.z);  PACK2(c3b, w2.z, w3.z);
    PACK2(c4a, w0.w, w1.w);  PACK2(c4b, w2.w, w3.w);

    if (base + CHUNK <= total4) {
        // hot path: front-batch ALL loads (MLP = ITERS), then independent chains
        float xv[ITERS];
        #pragma unroll
        for (int i = 0; i < ITERS; ++i)
            xv[i] = __ldcs(x + t0 + (NT / 10) * i);

        #pragma unroll
        for (int i = 0; i < ITERS; ++i)
            eval_store(xv[i], c0a,c0b,c1a,c1b,c2a,c2b,c3a,c3b,c4a,c4b,
                       out4 + base + i * NT + tid);
    } else {
        #pragma unroll
        for (int i = 0; i < ITERS; ++i) {
            const int g = base + i * NT + tid;
            if (g < total4)
                eval_store(__ldcs(x + t0 + (NT / 10) * i),
                           c0a,c0b,c1a,c1b,c2a,c2b,c3a,c3b,c4a,c4b,
                           out4 + g);
        }
    }
}

extern "C" void kernel_launch(void* const* d_in, const int* in_sizes, int n_in,
                              void* d_out, int out_size)
{
    const float* x    = (const float*)d_in[0];
    // d_in[1] = q_weights: unused (global phase cancels in |psi|^2)
    const float* W    = (const float*)d_in[2];
    const float* bias = (const float*)d_in[3];
    float4* out4      = (float4*)d_out;

    const int seq    = in_sizes[0];
    const int total4 = seq * 10;
    const int blocks = (total4 + CHUNK - 1) / CHUNK;   // 4096 for SEQ=2^20
    qmodel_kernel<<<blocks, NT>>>(x, W, bias, out4, total4);
}

// round 8
// speedup vs baseline: 1.2119x; 1.1416x over previous
#include <cuda_runtime.h>
#include <cstdint>

// out[t, v] = bias[v] + sum_{q=0..3} W[v][q] * cos(x[t])^(q+1)
// (closed form of the CNOT-permuted Ry product state; phase cancels in |psi|^2)
//
// DRAM-write-bound streaming kernel: 168MB out + 4MB in per launch
// (~5.9 TB/s sustained over the replay period = the effective wall).
// Empirically optimal configuration (R5):
//   NT=160 (5 warps, regs~40 -> 12 CTAs/SM), ITERS=8, grid 8192
//   thread owns fixed v-group vv=tid%10, coeffs packed in regs as f32x2
//   8 front-batched LDG.32 of x (MLP=8, 10-lane broadcast, ~1 sector/warp)
//   then 8 independent [5-FMA cos poly -> 8 fma.f32x2 Horner -> STG.128] chains
//   warp stores 512 contiguous bytes, evict-first (__stcs, write-once data)

#define NT    160
#define ITERS 8
#define CHUNK (NT * ITERS)   // 1280 float4 per block; %10==0 -> vv loop-invariant

#define PACK2(o, lo, hi) \
    asm("mov.b64 %0, {%1, %2};" : "=l"(o) : "f"(lo), "f"(hi))
#define FMA2(d, a, b, c) \
    asm("fma.rn.f32x2 %0, %1, %2, %3;" : "=l"(d) : "l"(a), "l"(b), "l"(c))

__device__ __forceinline__ void eval_store(
    float xv,
    unsigned long long c0a, unsigned long long c0b,
    unsigned long long c1a, unsigned long long c1b,
    unsigned long long c2a, unsigned long long c2b,
    unsigned long long c3a, unsigned long long c3b,
    unsigned long long c4a, unsigned long long c4b,
    float4* __restrict__ dst)
{
    // cos(xv) for xv in [0,1): even Taylor, rel err < 3e-9
    const float y = xv * xv;
    float u = fmaf(y, -2.7557319e-07f,  2.4801587e-05f);
    u = fmaf(y, u, -1.3888889e-03f);
    u = fmaf(y, u,  4.1666667e-02f);
    u = fmaf(y, u, -5.0000000e-01f);
    u = fmaf(y, u,  1.0000000e+00f);

    unsigned long long pu;
    PACK2(pu, u, u);

    // Horner: r = c0 + u*(c1 + u*(c2 + u*(c3 + u*c4))), two packed halves
    unsigned long long r01, r23;
    FMA2(r01, c4a, pu, c3a);
    FMA2(r23, c4b, pu, c3b);
    FMA2(r01, r01, pu, c2a);
    FMA2(r23, r23, pu, c2b);
    FMA2(r01, r01, pu, c1a);
    FMA2(r23, r23, pu, c1b);
    FMA2(r01, r01, pu, c0a);
    FMA2(r23, r23, pu, c0b);

    float2 lo = *(float2*)&r01;
    float2 hi = *(float2*)&r23;
    __stcs(dst, make_float4(lo.x, lo.y, hi.x, hi.y));  // evict-first: write-once
}

__global__ void __launch_bounds__(NT)
qmodel_kernel(const float* __restrict__ x,
              const float* __restrict__ W,     // (40,4) row-major
              const float* __restrict__ bias,  // (40,)
              float4* __restrict__ out4,       // (SEQ*10,) float4
              int total4)                      // SEQ*10
{
    const int tid  = threadIdx.x;
    const int base = blockIdx.x * CHUNK;       // float4 index, % 10 == 0
    const int vv   = tid % 10;
    const int t0   = base / 10 + tid / 10;     // first t for this thread

    // ---- packed coefficients for outputs v0..v0+3 (loop-invariant) ----
    const int v0 = vv * 4;
    const float4 w0 = ((const float4*)W)[v0 + 0];
    const float4 w1 = ((const float4*)W)[v0 + 1];
    const float4 w2 = ((const float4*)W)[v0 + 2];
    const float4 w3 = ((const float4*)W)[v0 + 3];
    const float4 bb = *(const float4*)(bias + v0);

    unsigned long long c0a, c0b, c1a, c1b, c2a, c2b, c3a, c3b, c4a, c4b;
    PACK2(c0a, bb.x, bb.y);  PACK2(c0b, bb.z, bb.w);
    PACK2(c1a, w0.x, w1.x);  PACK2(c1b, w2.x, w3.x);
    PACK2(c2a, w0.y, w1.y);  PACK2(c2b, w2.y, w3.y);
    PACK2(c3a, w0.z, w1.z);  PACK2(c3b, w2.z, w3.z);
    PACK2(c4a, w0.w, w1.w);  PACK2(c4b, w2.w, w3.w);

    if (base + CHUNK <= total4) {
        // hot path: front-batch ALL loads (MLP = ITERS), then independent chains
        float xv[ITERS];
        #pragma unroll
        for (int i = 0; i < ITERS; ++i)
            xv[i] = x[t0 + (NT / 10) * i];

        #pragma unroll
        for (int i = 0; i < ITERS; ++i)
            eval_store(xv[i], c0a,c0b,c1a,c1b,c2a,c2b,c3a,c3b,c4a,c4b,
                       out4 + base + i * NT + tid);
    } else {
        #pragma unroll
        for (int i = 0; i < ITERS; ++i) {
            const int g = base + i * NT + tid;
            if (g < total4)
                eval_store(x[t0 + (NT / 10) * i],
                           c0a,c0b,c1a,c1b,c2a,c2b,c3a,c3b,c4a,c4b,
                           out4 + g);
        }
    }
}

extern "C" void kernel_launch(void* const* d_in, const int* in_sizes, int n_in,
                              void* d_out, int out_size)
{
    const float* x    = (const float*)d_in[0];
    // d_in[1] = q_weights: unused (global phase cancels in |psi|^2)
    const float* W    = (const float*)d_in[2];
    const float* bias = (const float*)d_in[3];
    float4* out4      = (float4*)d_out;

    const int seq    = in_sizes[0];
    const int total4 = seq * 10;
    const int blocks = (total4 + CHUNK - 1) / CHUNK;   // 8192 for SEQ=2^20
    qmodel_kernel<<<blocks, NT>>>(x, W, bias, out4, total4);
}